// round 4
// baseline (speedup 1.0000x reference)
#include <cuda_runtime.h>
#include <math.h>

// ---------------- problem constants ----------------
#define T_STEPS 16384
#define HDIM    1028
#define G4      4112          // 4*HDIM
#define KPAD    1032          // HDIM padded to multiple of 8 for GEMM
#define GRID_R  147           // persistent CTAs (<= SM count, 1 CTA/SM)
#define UPER    7             // hidden units per CTA (147*7 = 1029 >= 1028)
#define NW      21            // warps per CTA
#define NT      672           // threads per CTA
#define CPW     52            // columns (of h) per warp: 21*52 = 1092 >= 1028
#define HB      1092          // padded h broadcast buffer length

// ---------------- device scratch (static: no allocation allowed) ----------------
__device__ __align__(16) float g_h1[(long long)T_STEPS * KPAD];   // layer-0 outputs, K-padded
__device__ __align__(16) float g_ihc[(long long)T_STEPS * G4];    // w_ih1 @ h1  (precomputed)
__device__ __align__(16) float g_h2[(long long)T_STEPS * HDIM];   // layer-1 outputs
__device__ __align__(16) float g_hbuf[2][HB];                     // double-buffered h broadcast
__device__ __align__(16) float g_wpad[(long long)G4 * KPAD];      // padded w_ih1
__device__ unsigned g_bar;                                        // grid barrier counter

// ---------------- pad w_ih1 to KPAD stride ----------------
__global__ void pad_w_kernel(const float* __restrict__ w) {
    int n = blockIdx.x;
    for (int k = threadIdx.x; k < KPAD; k += blockDim.x)
        g_wpad[(long long)n * KPAD + k] = (k < HDIM) ? w[(long long)n * HDIM + k] : 0.f;
}

// ---------------- persistent LSTM recurrence ----------------
// One CTA per SM. Each CTA owns UPER hidden units = 4*UPER = 28 gate rows.
// Lane l (<28) <-> gate row (g = l/7, uu = l%7, global row = g*HDIM + s*UPER + uu).
// Warp w owns h-columns [w*CPW, w*CPW+CPW). Weights live in registers.
__global__ void __launch_bounds__(NT, 1) lstm_rec_kernel(
    const float* __restrict__ w_hh,   // [4112][1028]
    const float* __restrict__ w_ih0,  // [4112] (layer 0 only)
    const float* __restrict__ b0,     // b_ih [4112]
    const float* __restrict__ b1,     // b_hh [4112]
    const float* __restrict__ xin,    // layer0: x[T]; layer1: g_ihc [T][4112]
    float* __restrict__ hout,         // layer0: g_h1 (stride KPAD); layer1: g_h2 (stride HDIM)
    int hstride, int layer)
{
    __shared__ float xc_s[32];
    __shared__ float partial_s[NW * 32];

    const int tid = threadIdx.x;
    const int w   = tid >> 5;
    const int l   = tid & 31;
    const int s   = blockIdx.x;

    const int g  = l / 7;
    const int uu = l - g * 7;
    const int u  = s * UPER + uu;
    const bool rowvalid = (l < 28) && (u < HDIM);
    const int grow = g * HDIM + u;          // only meaningful when rowvalid
    const int c0 = w * CPW;

    // --- load recurrent weights into registers (one-time) ---
    float wreg[CPW];
    #pragma unroll
    for (int j = 0; j < CPW; ++j) {
        int c = c0 + j;
        wreg[j] = (rowvalid && c < HDIM) ? w_hh[(long long)grow * HDIM + c] : 0.f;
    }
    // per-row input weight (layer 0) and bias sum
    float wih = 0.f, bsum = 0.f;
    if (rowvalid) {
        bsum = b0[grow] + b1[grow];
        if (layer == 0) wih = w_ih0[grow];
    }

    float creg = 0.f;   // cell state, valid in warp-0 lanes < 7

    for (int t = 0; t < T_STEPS; ++t) {
        // --- warp 1: produce input contribution xc for the 28 rows ---
        if (w == 1) {
            float v = 0.f;
            if (rowvalid) {
                if (layer == 0) {
                    float xv = __ldg(&xin[t]);
                    v = fmaf(xv, wih, bsum);
                } else {
                    v = __ldg(&xin[(long long)t * G4 + grow]) + bsum;
                }
            }
            xc_s[l] = v;
        }

        // --- all warps: partial dot products over own column chunk ---
        // h broadcast lives in L2; L1 is NOT coherent across SMs -> __ldcg.
        const float4* hb4 = reinterpret_cast<const float4*>(&g_hbuf[t & 1][c0]);
        float a0 = 0.f, a1 = 0.f;
        #pragma unroll
        for (int j4 = 0; j4 < CPW / 4; ++j4) {
            float4 hv = __ldcg(hb4 + j4);
            a0 = fmaf(wreg[4 * j4 + 0], hv.x, a0);
            a1 = fmaf(wreg[4 * j4 + 1], hv.y, a1);
            a0 = fmaf(wreg[4 * j4 + 2], hv.z, a0);
            a1 = fmaf(wreg[4 * j4 + 3], hv.w, a1);
        }
        partial_s[(w << 5) + l] = a0 + a1;
        __syncthreads();

        // --- warp 0: reduce across warps, gates, state update ---
        if (w == 0) {
            float sv = xc_s[l];
            #pragma unroll
            for (int ww = 0; ww < NW; ++ww) sv += partial_s[(ww << 5) + l];
            // gather the 4 gates of unit uu=l (lanes l, l+7, l+14, l+21)
            float iv = __shfl_sync(0xffffffffu, sv, l);
            float fv = __shfl_sync(0xffffffffu, sv, l + 7);
            float gv = __shfl_sync(0xffffffffu, sv, l + 14);
            float ov = __shfl_sync(0xffffffffu, sv, l + 21);
            if (l < 7) {
                int uo = s * UPER + l;
                if (uo < HDIM) {
                    iv = 1.f / (1.f + expf(-iv));
                    fv = 1.f / (1.f + expf(-fv));
                    gv = tanhf(gv);
                    ov = 1.f / (1.f + expf(-ov));
                    float c2 = fmaf(fv, creg, iv * gv);
                    creg = c2;
                    float hh = ov * tanhf(c2);
                    g_hbuf[(t + 1) & 1][uo] = hh;
                    hout[(long long)t * hstride + uo] = hh;
                }
            }
            __threadfence();   // make h writes visible before barrier arrive
        }
        __syncthreads();

        // --- grid-wide barrier (monotonic counter) ---
        if (tid == 0) {
            atomicAdd(&g_bar, 1u);
            unsigned tgt = (unsigned)(t + 1) * (unsigned)GRID_R;
            while (*((volatile unsigned*)&g_bar) < tgt) { }
            __threadfence();
        }
        __syncthreads();
    }
}

// ---------------- fp32 SGEMM: g_ihc[T][4112] = g_h1[T][KPAD] * g_wpad[4112][KPAD]^T ----------------
__global__ void __launch_bounds__(256, 2) sgemm_kernel(float* __restrict__ C)
{
    __shared__ float As[8][128];
    __shared__ float Bs[8][128];

    const int tid = threadIdx.x;
    const int m0 = blockIdx.y * 128;
    const int n0 = blockIdx.x * 128;

    const int lr = tid >> 1;            // 0..127
    const int lc = (tid & 1) * 4;       // 0 or 4
    const float* Ap = g_h1 + (long long)(m0 + lr) * KPAD + lc;
    const int brow = n0 + lr;
    const float* Bp = g_wpad + (long long)brow * KPAD + lc;
    const bool bvalid = (brow < G4);

    const int tx = tid & 15;            // n sub-tile
    const int ty = tid >> 4;            // m sub-tile

    float acc[8][8];
    #pragma unroll
    for (int i = 0; i < 8; ++i)
        #pragma unroll
        for (int j = 0; j < 8; ++j) acc[i][j] = 0.f;

    for (int k0 = 0; k0 < KPAD; k0 += 8) {
        float4 av = *reinterpret_cast<const float4*>(Ap + k0);
        float4 bv = bvalid ? *reinterpret_cast<const float4*>(Bp + k0)
                           : make_float4(0.f, 0.f, 0.f, 0.f);
        __syncthreads();
        As[lc + 0][lr] = av.x; As[lc + 1][lr] = av.y;
        As[lc + 2][lr] = av.z; As[lc + 3][lr] = av.w;
        Bs[lc + 0][lr] = bv.x; Bs[lc + 1][lr] = bv.y;
        Bs[lc + 2][lr] = bv.z; Bs[lc + 3][lr] = bv.w;
        __syncthreads();
        #pragma unroll
        for (int kk = 0; kk < 8; ++kk) {
            float ra[8], rb[8];
            #pragma unroll
            for (int i = 0; i < 8; ++i) ra[i] = As[kk][ty * 8 + i];
            #pragma unroll
            for (int j = 0; j < 8; ++j) rb[j] = Bs[kk][tx * 8 + j];
            #pragma unroll
            for (int i = 0; i < 8; ++i)
                #pragma unroll
                for (int j = 0; j < 8; ++j)
                    acc[i][j] = fmaf(ra[i], rb[j], acc[i][j]);
        }
    }

    #pragma unroll
    for (int i = 0; i < 8; ++i) {
        int m = m0 + ty * 8 + i;
        #pragma unroll
        for (int j = 0; j < 8; ++j) {
            int n = n0 + tx * 8 + j;
            if (n < G4) C[(long long)m * G4 + n] = acc[i][j];
        }
    }
}

// ---------------- final linear: out[t] = h2[t] . lin_w + lin_b ----------------
__global__ void outdot_kernel(const float* __restrict__ lw,
                              const float* __restrict__ lb,
                              float* __restrict__ out)
{
    const int w = threadIdx.x >> 5;
    const int l = threadIdx.x & 31;
    const int t = blockIdx.x * 4 + w;
    if (t >= T_STEPS) return;
    const float* h = g_h2 + (long long)t * HDIM;
    float acc = 0.f;
    for (int u = l; u < HDIM; u += 32) acc = fmaf(h[u], lw[u], acc);
    #pragma unroll
    for (int o = 16; o; o >>= 1) acc += __shfl_down_sync(0xffffffffu, acc, o);
    if (l == 0) out[t] = acc + lb[0];
}

// ---------------- launch ----------------
extern "C" void kernel_launch(void* const* d_in, const int* in_sizes, int n_in,
                              void* d_out, int out_size)
{
    const float* x     = (const float*)d_in[0];
    const float* w_ih0 = (const float*)d_in[1];
    const float* w_hh0 = (const float*)d_in[2];
    const float* b_ih0 = (const float*)d_in[3];
    const float* b_hh0 = (const float*)d_in[4];
    const float* w_ih1 = (const float*)d_in[5];
    const float* w_hh1 = (const float*)d_in[6];
    const float* b_ih1 = (const float*)d_in[7];
    const float* b_hh1 = (const float*)d_in[8];
    const float* lin_w = (const float*)d_in[9];
    const float* lin_b = (const float*)d_in[10];
    float* out = (float*)d_out;

    void *p_h1, *p_ihc, *p_hbuf, *p_bar;
    cudaGetSymbolAddress(&p_h1,   g_h1);
    cudaGetSymbolAddress(&p_ihc,  g_ihc);
    cudaGetSymbolAddress(&p_hbuf, g_hbuf);
    cudaGetSymbolAddress(&p_bar,  g_bar);

    // zero: h1 (for K-padding), h broadcast buffer, barrier counter
    cudaMemsetAsync(p_h1,   0, sizeof(float) * (size_t)T_STEPS * KPAD);
    cudaMemsetAsync(p_hbuf, 0, sizeof(float) * 2 * HB);
    cudaMemsetAsync(p_bar,  0, sizeof(unsigned));

    // pad w_ih1 for the GEMM
    pad_w_kernel<<<G4, 256>>>(w_ih1);

    // layer-0 recurrence
    lstm_rec_kernel<<<GRID_R, NT>>>(w_hh0, w_ih0, b_ih0, b_hh0, x,
                                    (float*)p_h1, KPAD, 0);

    // ihc = h1 @ w_ih1^T (biases added inside recurrence kernel)
    dim3 gB(33, 128);
    sgemm_kernel<<<gB, 256>>>((float*)p_ihc);

    // reset barrier + h buffer for layer 1
    cudaMemsetAsync(p_hbuf, 0, sizeof(float) * 2 * HB);
    cudaMemsetAsync(p_bar,  0, sizeof(unsigned));

    // layer-1 recurrence
    void* p_h2; cudaGetSymbolAddress(&p_h2, g_h2);
    lstm_rec_kernel<<<GRID_R, NT>>>(w_hh1, nullptr, b_ih1, b_hh1,
                                    (const float*)p_ihc, (float*)p_h2, HDIM, 1);

    // final projection
    outdot_kernel<<<(T_STEPS + 3) / 4, 128>>>(lin_w, lin_b, out);
}